// round 8
// baseline (speedup 1.0000x reference)
#include <cuda_runtime.h>
#include <cuda_fp16.h>
#include <cstdint>

// Llama4 MoE: T=2048 tokens, D=2048, F=2048, E=8 (top-1) + shared expert.
// R6 (passing, 684us): fp16 ldmatrix GEMM, 2-stage cp.async, weight pre-convert.
// R7: (a) 6 conv launches merged into ONE kernel so ncu -s5 captures a GEMM;
//     (b) swiglu fused into up-GEMM epilogue (MODE 3) -> g_ubuf + k_swiglu gone.

#define T_TOK  2048
#define DMODEL 2048
#define FDIM   2048
#define NEXP   8

#define BM 128
#define BN 128
#define BK 32
#define ASTRIDE 40     // halves per smem A row (32 + 8 pad)
#define BSTRIDE_H 136  // halves per smem B row (128 + 8 pad)
#define ASZ (BM * ASTRIDE)       // 5120 halves / stage
#define BSZ (BK * BSTRIDE_H)     // 4352 halves / stage

// ---------------- scratch (device globals; no allocation allowed) ----------
__device__ __half g_xh [(size_t)T_TOK * DMODEL];
__device__ __half g_xg [(size_t)T_TOK * DMODEL];
__device__ float  g_gbuf[(size_t)T_TOK * FDIM];    // gate GEMM out (fp32)
__device__ __half g_h  [(size_t)T_TOK * FDIM];     // fp16(silu(g)*u)
// fp16 weight copies (converted once per launch)
__device__ __half g_wg16[(size_t)NEXP * DMODEL * FDIM];
__device__ __half g_wu16[(size_t)NEXP * DMODEL * FDIM];
__device__ __half g_wd16[(size_t)NEXP * FDIM * DMODEL];
__device__ __half g_sg16[(size_t)DMODEL * FDIM];
__device__ __half g_su16[(size_t)DMODEL * FDIM];
__device__ __half g_sd16[(size_t)FDIM * DMODEL];
__device__ int    g_idx[T_TOK];
__device__ int    g_perm[T_TOK];
__device__ float  g_score[T_TOK];
__device__ int    g_counts[NEXP];
__device__ int    g_cursor[NEXP];
__device__ int    g_off[NEXP + 1];
__device__ int    g_off_shared[2] = {0, T_TOK};

// ---------------------------------------------------------------------------
__global__ void k_zero() {
    if (threadIdx.x < NEXP) { g_counts[threadIdx.x] = 0; g_cursor[threadIdx.x] = 0; }
}

// All 6 fp32->fp16 weight conversions in ONE launch (keeps GEMM at launch #6
// for ncu -s 5 -c 1, and drops 5 launch overheads).
struct ConvJobs {
    const float* src[6];
    __half*      dst[6];
    size_t       n4[6];
};
__global__ void k_conv_all(ConvJobs j) {
    size_t tid0 = (size_t)blockIdx.x * blockDim.x + threadIdx.x;
    size_t gs   = (size_t)gridDim.x * blockDim.x;
#pragma unroll
    for (int q = 0; q < 6; q++) {
        const float* src = j.src[q];
        __half* dst = j.dst[q];
        size_t n4 = j.n4[q];
        for (size_t i = tid0; i < n4; i += gs) {
            float4 v = ((const float4*)src)[i];
            __half2 h0 = __floats2half2_rn(v.x, v.y);
            __half2 h1 = __floats2half2_rn(v.z, v.w);
            uint2 o;
            o.x = *(uint32_t*)&h0;
            o.y = *(uint32_t*)&h1;
            ((uint2*)dst)[i] = o;
        }
    }
}

__global__ void k_router(const float* __restrict__ x, const float* __restrict__ rw) {
    int t = blockIdx.x;
    const float* xr = x + (size_t)t * DMODEL;
    float acc[NEXP];
#pragma unroll
    for (int e = 0; e < NEXP; e++) acc[e] = 0.f;

    for (int k = threadIdx.x; k < DMODEL; k += 128) {
        float xv = xr[k];
        g_xh[(size_t)t * DMODEL + k] = __float2half(xv);
        const float4* w = (const float4*)(rw + (size_t)k * NEXP);
        float4 w0 = w[0], w1 = w[1];
        acc[0] += xv * w0.x; acc[1] += xv * w0.y;
        acc[2] += xv * w0.z; acc[3] += xv * w0.w;
        acc[4] += xv * w1.x; acc[5] += xv * w1.y;
        acc[6] += xv * w1.z; acc[7] += xv * w1.w;
    }
#pragma unroll
    for (int off = 16; off; off >>= 1)
#pragma unroll
        for (int e = 0; e < NEXP; e++)
            acc[e] += __shfl_xor_sync(0xffffffffu, acc[e], off);

    __shared__ float sred[4][NEXP];
    int wid = threadIdx.x >> 5, lane = threadIdx.x & 31;
    if (lane == 0)
#pragma unroll
        for (int e = 0; e < NEXP; e++) sred[wid][e] = acc[e];
    __syncthreads();
    if (threadIdx.x == 0) {
        float l[NEXP];
#pragma unroll
        for (int e = 0; e < NEXP; e++)
            l[e] = sred[0][e] + sred[1][e] + sred[2][e] + sred[3][e];
        int best = 0; float bv = l[0];
#pragma unroll
        for (int e = 1; e < NEXP; e++) if (l[e] > bv) { bv = l[e]; best = e; }
        g_idx[t] = best;
        g_score[t] = 1.f / (1.f + expf(-bv));
        atomicAdd(&g_counts[best], 1);
    }
}

__global__ void k_scan() {
    if (threadIdx.x == 0) {
        int r = 0; g_off[0] = 0;
        for (int e = 0; e < NEXP; e++) { r += g_counts[e]; g_off[e + 1] = r; }
    }
}

__global__ void k_gather(const float* __restrict__ x) {
    int t = blockIdx.x;
    __shared__ int sp;
    if (threadIdx.x == 0) {
        int e = g_idx[t];
        sp = g_off[e] + atomicAdd(&g_cursor[e], 1);
        g_perm[sp] = t;
    }
    __syncthreads();
    int p = sp;
    float s = g_score[t];
    const float* xr = x + (size_t)t * DMODEL;
    __half* dst = g_xg + (size_t)p * DMODEL;
    for (int k = threadIdx.x; k < DMODEL; k += 128)
        dst[k] = __float2half(xr[k] * s);
}

// ---------------------------------------------------------------------------
__device__ __forceinline__ void mma16816(float* c, const uint32_t* a, const uint32_t* b) {
    asm volatile(
        "mma.sync.aligned.m16n8k16.row.col.f32.f16.f16.f32 "
        "{%0,%1,%2,%3}, {%4,%5,%6,%7}, {%8,%9}, {%0,%1,%2,%3};\n"
        : "+f"(c[0]), "+f"(c[1]), "+f"(c[2]), "+f"(c[3])
        : "r"(a[0]), "r"(a[1]), "r"(a[2]), "r"(a[3]), "r"(b[0]), "r"(b[1]));
}

__device__ __forceinline__ void ldsm_x4(uint32_t* r, const void* p) {
    uint32_t a = (uint32_t)__cvta_generic_to_shared(p);
    asm volatile("ldmatrix.sync.aligned.m8n8.x4.shared.b16 {%0,%1,%2,%3}, [%4];\n"
                 : "=r"(r[0]), "=r"(r[1]), "=r"(r[2]), "=r"(r[3]) : "r"(a));
}
__device__ __forceinline__ void ldsm_x4_t(uint32_t* r, const void* p) {
    uint32_t a = (uint32_t)__cvta_generic_to_shared(p);
    asm volatile("ldmatrix.sync.aligned.m8n8.x4.trans.shared.b16 {%0,%1,%2,%3}, [%4];\n"
                 : "=r"(r[0]), "=r"(r[1]), "=r"(r[2]), "=r"(r[3]) : "r"(a));
}

__device__ __forceinline__ void cp16(void* smem_dst, const void* gsrc, int src_sz) {
    uint32_t s = (uint32_t)__cvta_generic_to_shared(smem_dst);
    asm volatile("cp.async.cg.shared.global [%0], [%1], 16, %2;\n"
                 :: "r"(s), "l"(gsrc), "r"(src_sz));
}
__device__ __forceinline__ void cp_commit() { asm volatile("cp.async.commit_group;\n"); }
template <int N>
__device__ __forceinline__ void cp_wait() {
    asm volatile("cp.async.wait_group %0;\n" :: "n"(N));
}

__device__ __forceinline__ float silu_f(float g) { return g / (1.f + expf(-g)); }

// Grouped GEMM, all-fp16 operands, fp32 accum, 2-stage cp.async.
// MODE 0: gate -> g_gbuf (fp32).
// MODE 3: up; epilogue h = fp16(silu(gbuf) * u) -> g_h   (fused swiglu).
// MODE 1: down, plain store to out. MODE 2: down, scatter out[perm[r]] += v.
template <int MODE>
__global__ __launch_bounds__(256) void k_gemm(
    int asel,                       // A: 0=g_xg, 1=g_xh, 2=g_h
    const __half* __restrict__ B0,
    long bexp_stride,
    int offsel,                     // 0=g_off (routed), 1=shared {0,T}
    float* __restrict__ out)
{
    __shared__ __half As[2 * ASZ];
    __shared__ __half Bs[2 * BSZ];

    const int* offs = offsel ? g_off_shared : g_off;
    int e    = blockIdx.z;
    int r0   = offs[e] + blockIdx.y * BM;
    int rend = offs[e + 1];
    if (r0 >= rend) return;

    const __half* A = (asel == 0) ? g_xg : (asel == 1) ? g_xh : g_h;
    const __half* B = B0 + (long)e * bexp_stride;
    int nb = blockIdx.x * BN;

    int tid = threadIdx.x;
    int lane = tid & 31, wid = tid >> 5;
    int wm = wid & 1, wn = wid >> 1;       // warp tile: 64x32
    int gid = lane >> 2, tig = lane & 3;

    // per-thread cp.async coordinates
    int a_row0 = (tid * 2) >> 2,     a_cc0 = (tid * 2) & 3;
    int a_row1 = (tid * 2 + 1) >> 2, a_cc1 = (tid * 2 + 1) & 3;
    int b_row = tid >> 3, b_c = (tid & 7) * 16;

    // ldmatrix lane decomposition
    int rr = lane & 7, s1 = (lane >> 3) & 1, s2 = lane >> 4;

    float c[4][4][4];
#pragma unroll
    for (int mi = 0; mi < 4; mi++)
#pragma unroll
        for (int ni = 0; ni < 4; ni++)
#pragma unroll
            for (int j = 0; j < 4; j++) c[mi][ni][j] = 0.f;

    auto issue_tiles = [&](int kb, int st) {
        // A tile: 128x32 halves; zero-fill rows beyond segment
        {
            int gr = r0 + a_row0;
            int ok = gr < rend;
            cp16(As + st * ASZ + a_row0 * ASTRIDE + a_cc0 * 8,
                 A + (size_t)(ok ? gr : r0) * DMODEL + kb * BK + a_cc0 * 8,
                 ok ? 16 : 0);
            gr = r0 + a_row1;
            ok = gr < rend;
            cp16(As + st * ASZ + a_row1 * ASTRIDE + a_cc1 * 8,
                 A + (size_t)(ok ? gr : r0) * DMODEL + kb * BK + a_cc1 * 8,
                 ok ? 16 : 0);
        }
        // B tile: 32k x 128n halves (2 chunks/thread)
        {
            const __half* src = B + (size_t)(kb * BK + b_row) * 2048 + nb + b_c;
            __half* dst = Bs + st * BSZ + b_row * BSTRIDE_H + b_c;
            cp16(dst,     src,     16);
            cp16(dst + 8, src + 8, 16);
        }
        cp_commit();
    };

    const int NKB = DMODEL / BK;   // 64
    issue_tiles(0, 0);

    for (int kb = 0; kb < NKB; kb++) {
        int cur = kb & 1;
        if (kb + 1 < NKB) {
            issue_tiles(kb + 1, cur ^ 1);
            cp_wait<1>();
        } else {
            cp_wait<0>();
        }
        __syncthreads();

        const __half* Ast = As + cur * ASZ;
        const __half* Bst = Bs + cur * BSZ;

#pragma unroll
        for (int ks = 0; ks < 2; ks++) {
            int k0 = ks * 16;
            uint32_t af[4][4];
#pragma unroll
            for (int mi = 0; mi < 4; mi++) {
                int m = wm * 64 + mi * 16 + rr + s1 * 8;
                ldsm_x4(af[mi], Ast + m * ASTRIDE + k0 + s2 * 8);
            }
            uint32_t bf[4][2];
#pragma unroll
            for (int nj = 0; nj < 2; nj++) {
                int kk = k0 + s1 * 8 + rr;
                int n0 = wn * 32 + nj * 16 + s2 * 8;
                uint32_t q[4];
                ldsm_x4_t(q, Bst + kk * BSTRIDE_H + n0);
                bf[nj * 2][0]     = q[0]; bf[nj * 2][1]     = q[1];
                bf[nj * 2 + 1][0] = q[2]; bf[nj * 2 + 1][1] = q[3];
            }
#pragma unroll
            for (int mi = 0; mi < 4; mi++)
#pragma unroll
                for (int ni = 0; ni < 4; ni++)
                    mma16816(c[mi][ni], af[mi], bf[ni]);
        }
        __syncthreads();
    }

    // --- epilogue ---
#pragma unroll
    for (int mi = 0; mi < 4; mi++) {
#pragma unroll
        for (int ni = 0; ni < 4; ni++) {
            int rrow = r0 + wm * 64 + mi * 16 + gid;
            int cc = nb + wn * 32 + ni * 8 + tig * 2;
            float* cp = c[mi][ni];
            if (MODE == 0) {
                if (rrow < rend) {
                    g_gbuf[(size_t)rrow * FDIM + cc]     = cp[0];
                    g_gbuf[(size_t)rrow * FDIM + cc + 1] = cp[1];
                }
                if (rrow + 8 < rend) {
                    g_gbuf[(size_t)(rrow + 8) * FDIM + cc]     = cp[2];
                    g_gbuf[(size_t)(rrow + 8) * FDIM + cc + 1] = cp[3];
                }
            } else if (MODE == 3) {
                if (rrow < rend) {
                    size_t o = (size_t)rrow * FDIM + cc;
                    g_h[o]     = __float2half(silu_f(g_gbuf[o])     * cp[0]);
                    g_h[o + 1] = __float2half(silu_f(g_gbuf[o + 1]) * cp[1]);
                }
                if (rrow + 8 < rend) {
                    size_t o = (size_t)(rrow + 8) * FDIM + cc;
                    g_h[o]     = __float2half(silu_f(g_gbuf[o])     * cp[2]);
                    g_h[o + 1] = __float2half(silu_f(g_gbuf[o + 1]) * cp[3]);
                }
            } else if (MODE == 1) {
                if (rrow < rend) {
                    out[(size_t)rrow * DMODEL + cc]     = cp[0];
                    out[(size_t)rrow * DMODEL + cc + 1] = cp[1];
                }
                if (rrow + 8 < rend) {
                    out[(size_t)(rrow + 8) * DMODEL + cc]     = cp[2];
                    out[(size_t)(rrow + 8) * DMODEL + cc + 1] = cp[3];
                }
            } else {   // MODE 2
                if (rrow < rend) {
                    int tk = g_perm[rrow];
                    float* o = out + (size_t)tk * DMODEL + cc;
                    o[0] += cp[0]; o[1] += cp[1];
                }
                if (rrow + 8 < rend) {
                    int tk = g_perm[rrow + 8];
                    float* o = out + (size_t)tk * DMODEL + cc;
                    o[0] += cp[2]; o[1] += cp[3];
                }
            }
        }
    }
}

// ---------------------------------------------------------------------------
extern "C" void kernel_launch(void* const* d_in, const int* in_sizes, int n_in,
                              void* d_out, int out_size) {
    const float* x   = (const float*)d_in[0];
    const float* rw  = (const float*)d_in[1];
    const float* gw  = (const float*)d_in[2];
    const float* uw  = (const float*)d_in[3];
    const float* dw  = (const float*)d_in[4];
    const float* sgw = (const float*)d_in[5];
    const float* suw = (const float*)d_in[6];
    const float* sdw = (const float*)d_in[7];
    float* out = (float*)d_out;

    __half *wg16, *wu16, *wd16, *sg16, *su16, *sd16;
    cudaGetSymbolAddress((void**)&wg16, g_wg16);
    cudaGetSymbolAddress((void**)&wu16, g_wu16);
    cudaGetSymbolAddress((void**)&wd16, g_wd16);
    cudaGetSymbolAddress((void**)&sg16, g_sg16);
    cudaGetSymbolAddress((void**)&su16, g_su16);
    cudaGetSymbolAddress((void**)&sd16, g_sd16);

    const size_t NR4 = (size_t)NEXP * DMODEL * FDIM / 4;
    const size_t NS4 = (size_t)DMODEL * FDIM / 4;
    ConvJobs cj;
    cj.src[0] = gw;  cj.dst[0] = wg16; cj.n4[0] = NR4;
    cj.src[1] = uw;  cj.dst[1] = wu16; cj.n4[1] = NR4;
    cj.src[2] = dw;  cj.dst[2] = wd16; cj.n4[2] = NR4;
    cj.src[3] = sgw; cj.dst[3] = sg16; cj.n4[3] = NS4;
    cj.src[4] = suw; cj.dst[4] = su16; cj.n4[4] = NS4;
    cj.src[5] = sdw; cj.dst[5] = sd16; cj.n4[5] = NS4;

    k_conv_all<<<4096, 256>>>(cj);                 // launch 1
    k_zero<<<1, 32>>>();                           // launch 2
    k_router<<<T_TOK, 128>>>(x, rw);               // launch 3
    k_scan<<<1, 1>>>();                            // launch 4
    k_gather<<<T_TOK, 128>>>(x);                   // launch 5

    // shared expert: gate -> up+swiglu -> down (plain store initializes out)
    k_gemm<0><<<dim3(FDIM / BN, T_TOK / BM, 1), 256>>>(1, sg16, 0L, 1, nullptr);  // launch 6 (ncu)
    k_gemm<3><<<dim3(FDIM / BN, T_TOK / BM, 1), 256>>>(1, su16, 0L, 1, nullptr);
    k_gemm<1><<<dim3(DMODEL / BN, T_TOK / BM, 1), 256>>>(2, sd16, 0L, 1, out);

    // routed experts (grouped): gate -> up+swiglu -> down (scatter +=)
    k_gemm<0><<<dim3(FDIM / BN, T_TOK / BM, NEXP), 256>>>(0, wg16, (long)DMODEL * FDIM, 0, nullptr);
    k_gemm<3><<<dim3(FDIM / BN, T_TOK / BM, NEXP), 256>>>(0, wu16, (long)DMODEL * FDIM, 0, nullptr);
    k_gemm<2><<<dim3(DMODEL / BN, T_TOK / BM, NEXP), 256>>>(2, wd16, (long)FDIM * DMODEL, 0, out);
}

// round 14
// speedup vs baseline: 1.0358x; 1.0358x over previous
#include <cuda_runtime.h>
#include <cuda_fp16.h>
#include <cstdint>

// Llama4 MoE: T=2048, D=F=2048, E=8 top-1 + shared expert.
// R8: dual-accumulator FUSED gate+up GEMM (A tile loaded once, both B tiles,
// silu*mul in-register, fp16 h written directly; g_gbuf eliminated).
// Launch order puts the fused shared GEMM at launch #4 (ncu captures #4).
// R9-R13: resubmit unchanged (broker timeouts; R8 never measured).

#define T_TOK  2048
#define DMODEL 2048
#define FDIM   2048
#define NEXP   8

#define BM 128
#define BN 128
#define BK 32
#define ASTRIDE 40     // halves per smem A row (32 + 8 pad)
#define BSTRIDE_H 136  // halves per smem B row (128 + 8 pad)
#define ASZ (BM * ASTRIDE)       // 5120 halves / stage
#define BSZ (BK * BSTRIDE_H)     // 4352 halves / stage
#define GU_SMEM_BYTES ((2 * ASZ + 4 * BSZ) * 2)   // 55296 B (dynamic)

// ---------------- scratch (device globals; no allocation allowed) ----------
__device__ __half g_xh [(size_t)T_TOK * DMODEL];
__device__ __half g_xg [(size_t)T_TOK * DMODEL];
__device__ __half g_h  [(size_t)T_TOK * FDIM];     // fp16(silu(g)*u)
__device__ __half g_wg16[(size_t)NEXP * DMODEL * FDIM];
__device__ __half g_wu16[(size_t)NEXP * DMODEL * FDIM];
__device__ __half g_wd16[(size_t)NEXP * FDIM * DMODEL];
__device__ __half g_sg16[(size_t)DMODEL * FDIM];
__device__ __half g_su16[(size_t)DMODEL * FDIM];
__device__ __half g_sd16[(size_t)FDIM * DMODEL];
__device__ int    g_idx[T_TOK];
__device__ int    g_perm[T_TOK];
__device__ float  g_score[T_TOK];
__device__ int    g_counts[NEXP];
__device__ int    g_cursor[NEXP];
__device__ int    g_off[NEXP + 1];
__device__ int    g_off_shared[2] = {0, T_TOK};

// ---------------------------------------------------------------------------
// All 6 fp32->fp16 weight conversions in ONE launch; also zeroes counters.
struct ConvJobs {
    const float* src[6];
    __half*      dst[6];
    size_t       n4[6];
};
__global__ void k_conv_all(ConvJobs j) {
    if (blockIdx.x == 0 && threadIdx.x < NEXP) {
        g_counts[threadIdx.x] = 0;
        g_cursor[threadIdx.x] = 0;
    }
    size_t tid0 = (size_t)blockIdx.x * blockDim.x + threadIdx.x;
    size_t gs   = (size_t)gridDim.x * blockDim.x;
#pragma unroll
    for (int q = 0; q < 6; q++) {
        const float* src = j.src[q];
        __half* dst = j.dst[q];
        size_t n4 = j.n4[q];
        for (size_t i = tid0; i < n4; i += gs) {
            float4 v = ((const float4*)src)[i];
            __half2 h0 = __floats2half2_rn(v.x, v.y);
            __half2 h1 = __floats2half2_rn(v.z, v.w);
            uint2 o;
            o.x = *(uint32_t*)&h0;
            o.y = *(uint32_t*)&h1;
            ((uint2*)dst)[i] = o;
        }
    }
}

__global__ void k_router(const float* __restrict__ x, const float* __restrict__ rw) {
    int t = blockIdx.x;
    const float* xr = x + (size_t)t * DMODEL;
    float acc[NEXP];
#pragma unroll
    for (int e = 0; e < NEXP; e++) acc[e] = 0.f;

    for (int k = threadIdx.x; k < DMODEL; k += 128) {
        float xv = xr[k];
        g_xh[(size_t)t * DMODEL + k] = __float2half(xv);
        const float4* w = (const float4*)(rw + (size_t)k * NEXP);
        float4 w0 = w[0], w1 = w[1];
        acc[0] += xv * w0.x; acc[1] += xv * w0.y;
        acc[2] += xv * w0.z; acc[3] += xv * w0.w;
        acc[4] += xv * w1.x; acc[5] += xv * w1.y;
        acc[6] += xv * w1.z; acc[7] += xv * w1.w;
    }
#pragma unroll
    for (int off = 16; off; off >>= 1)
#pragma unroll
        for (int e = 0; e < NEXP; e++)
            acc[e] += __shfl_xor_sync(0xffffffffu, acc[e], off);

    __shared__ float sred[4][NEXP];
    int wid = threadIdx.x >> 5, lane = threadIdx.x & 31;
    if (lane == 0)
#pragma unroll
        for (int e = 0; e < NEXP; e++) sred[wid][e] = acc[e];
    __syncthreads();
    if (threadIdx.x == 0) {
        float l[NEXP];
#pragma unroll
        for (int e = 0; e < NEXP; e++)
            l[e] = sred[0][e] + sred[1][e] + sred[2][e] + sred[3][e];
        int best = 0; float bv = l[0];
#pragma unroll
        for (int e = 1; e < NEXP; e++) if (l[e] > bv) { bv = l[e]; best = e; }
        g_idx[t] = best;
        g_score[t] = 1.f / (1.f + expf(-bv));
        atomicAdd(&g_counts[best], 1);
    }
}

__global__ void k_scan() {
    if (threadIdx.x == 0) {
        int r = 0; g_off[0] = 0;
        for (int e = 0; e < NEXP; e++) { r += g_counts[e]; g_off[e + 1] = r; }
    }
}

__global__ void k_gather(const float* __restrict__ x) {
    int t = blockIdx.x;
    __shared__ int sp;
    if (threadIdx.x == 0) {
        int e = g_idx[t];
        sp = g_off[e] + atomicAdd(&g_cursor[e], 1);
        g_perm[sp] = t;
    }
    __syncthreads();
    int p = sp;
    float s = g_score[t];
    const float* xr = x + (size_t)t * DMODEL;
    __half* dst = g_xg + (size_t)p * DMODEL;
    for (int k = threadIdx.x; k < DMODEL; k += 128)
        dst[k] = __float2half(xr[k] * s);
}

// ---------------------------------------------------------------------------
__device__ __forceinline__ void mma16816(float* c, const uint32_t* a, const uint32_t* b) {
    asm volatile(
        "mma.sync.aligned.m16n8k16.row.col.f32.f16.f16.f32 "
        "{%0,%1,%2,%3}, {%4,%5,%6,%7}, {%8,%9}, {%0,%1,%2,%3};\n"
        : "+f"(c[0]), "+f"(c[1]), "+f"(c[2]), "+f"(c[3])
        : "r"(a[0]), "r"(a[1]), "r"(a[2]), "r"(a[3]), "r"(b[0]), "r"(b[1]));
}
__device__ __forceinline__ void ldsm_x4(uint32_t* r, const void* p) {
    uint32_t a = (uint32_t)__cvta_generic_to_shared(p);
    asm volatile("ldmatrix.sync.aligned.m8n8.x4.shared.b16 {%0,%1,%2,%3}, [%4];\n"
                 : "=r"(r[0]), "=r"(r[1]), "=r"(r[2]), "=r"(r[3]) : "r"(a));
}
__device__ __forceinline__ void ldsm_x4_t(uint32_t* r, const void* p) {
    uint32_t a = (uint32_t)__cvta_generic_to_shared(p);
    asm volatile("ldmatrix.sync.aligned.m8n8.x4.trans.shared.b16 {%0,%1,%2,%3}, [%4];\n"
                 : "=r"(r[0]), "=r"(r[1]), "=r"(r[2]), "=r"(r[3]) : "r"(a));
}
__device__ __forceinline__ void cp16(void* smem_dst, const void* gsrc, int src_sz) {
    uint32_t s = (uint32_t)__cvta_generic_to_shared(smem_dst);
    asm volatile("cp.async.cg.shared.global [%0], [%1], 16, %2;\n"
                 :: "r"(s), "l"(gsrc), "r"(src_sz));
}
__device__ __forceinline__ void cp_commit() { asm volatile("cp.async.commit_group;\n"); }
template <int N>
__device__ __forceinline__ void cp_wait() {
    asm volatile("cp.async.wait_group %0;\n" :: "n"(N));
}
__device__ __forceinline__ float silu_f(float g) { return g / (1.f + expf(-g)); }

// ------------------- fused gate+up GEMM (dual accumulators) ----------------
// h[r, n] = fp16( silu(A@Bg) * (A@Bu) ), A fp16 [rows,2048], Bg/Bu fp16.
__global__ __launch_bounds__(256) void k_gemm_gu(
    int asel,                        // 1 = g_xh (shared), 0 = g_xg (routed)
    const __half* __restrict__ Bg0, const __half* __restrict__ Bu0,
    long bexp_stride, int offsel)
{
    extern __shared__ __half smem[];
    __half* As = smem;                   // 2 * ASZ
    __half* Bg = smem + 2 * ASZ;         // 2 * BSZ
    __half* Bu = smem + 2 * ASZ + 2 * BSZ;

    const int* offs = offsel ? g_off_shared : g_off;
    int e    = blockIdx.z;
    int r0   = offs[e] + blockIdx.y * BM;
    int rend = offs[e + 1];
    if (r0 >= rend) return;

    const __half* A  = asel ? g_xh : g_xg;
    const __half* BG = Bg0 + (long)e * bexp_stride;
    const __half* BU = Bu0 + (long)e * bexp_stride;
    int nb = blockIdx.x * BN;

    int tid = threadIdx.x;
    int lane = tid & 31, wid = tid >> 5;
    int wm = wid & 1, wn = wid >> 1;
    int gid = lane >> 2, tig = lane & 3;

    int a_row0 = (tid * 2) >> 2,     a_cc0 = (tid * 2) & 3;
    int a_row1 = (tid * 2 + 1) >> 2, a_cc1 = (tid * 2 + 1) & 3;
    int b_row = tid >> 3, b_c = (tid & 7) * 16;

    int rr = lane & 7, s1 = (lane >> 3) & 1, s2 = lane >> 4;

    float cg[4][4][4], cu[4][4][4];
#pragma unroll
    for (int mi = 0; mi < 4; mi++)
#pragma unroll
        for (int ni = 0; ni < 4; ni++)
#pragma unroll
            for (int j = 0; j < 4; j++) { cg[mi][ni][j] = 0.f; cu[mi][ni][j] = 0.f; }

    auto issue_tiles = [&](int kb, int st) {
        {
            int gr = r0 + a_row0;
            int ok = gr < rend;
            cp16(As + st * ASZ + a_row0 * ASTRIDE + a_cc0 * 8,
                 A + (size_t)(ok ? gr : r0) * DMODEL + kb * BK + a_cc0 * 8,
                 ok ? 16 : 0);
            gr = r0 + a_row1;
            ok = gr < rend;
            cp16(As + st * ASZ + a_row1 * ASTRIDE + a_cc1 * 8,
                 A + (size_t)(ok ? gr : r0) * DMODEL + kb * BK + a_cc1 * 8,
                 ok ? 16 : 0);
        }
        {
            size_t go = (size_t)(kb * BK + b_row) * 2048 + nb + b_c;
            __half* dg = Bg + st * BSZ + b_row * BSTRIDE_H + b_c;
            __half* du = Bu + st * BSZ + b_row * BSTRIDE_H + b_c;
            cp16(dg,     BG + go,     16);
            cp16(dg + 8, BG + go + 8, 16);
            cp16(du,     BU + go,     16);
            cp16(du + 8, BU + go + 8, 16);
        }
        cp_commit();
    };

    const int NKB = DMODEL / BK;   // 64
    issue_tiles(0, 0);

    for (int kb = 0; kb < NKB; kb++) {
        int cur = kb & 1;
        if (kb + 1 < NKB) {
            issue_tiles(kb + 1, cur ^ 1);
            cp_wait<1>();
        } else {
            cp_wait<0>();
        }
        __syncthreads();

        const __half* Ast = As + cur * ASZ;
        const __half* Bgs = Bg + cur * BSZ;
        const __half* Bus = Bu + cur * BSZ;

#pragma unroll
        for (int ks = 0; ks < 2; ks++) {
            int k0 = ks * 16;
            uint32_t af[4][4];
#pragma unroll
            for (int mi = 0; mi < 4; mi++) {
                int m = wm * 64 + mi * 16 + rr + s1 * 8;
                ldsm_x4(af[mi], Ast + m * ASTRIDE + k0 + s2 * 8);
            }
            int kk = k0 + s1 * 8 + rr;
            // gate
            {
                uint32_t bf[4][2];
#pragma unroll
                for (int nj = 0; nj < 2; nj++) {
                    int n0 = wn * 32 + nj * 16 + s2 * 8;
                    uint32_t q[4];
                    ldsm_x4_t(q, Bgs + kk * BSTRIDE_H + n0);
                    bf[nj * 2][0] = q[0]; bf[nj * 2][1] = q[1];
                    bf[nj * 2 + 1][0] = q[2]; bf[nj * 2 + 1][1] = q[3];
                }
#pragma unroll
                for (int mi = 0; mi < 4; mi++)
#pragma unroll
                    for (int ni = 0; ni < 4; ni++)
                        mma16816(cg[mi][ni], af[mi], bf[ni]);
            }
            // up
            {
                uint32_t bf[4][2];
#pragma unroll
                for (int nj = 0; nj < 2; nj++) {
                    int n0 = wn * 32 + nj * 16 + s2 * 8;
                    uint32_t q[4];
                    ldsm_x4_t(q, Bus + kk * BSTRIDE_H + n0);
                    bf[nj * 2][0] = q[0]; bf[nj * 2][1] = q[1];
                    bf[nj * 2 + 1][0] = q[2]; bf[nj * 2 + 1][1] = q[3];
                }
#pragma unroll
                for (int mi = 0; mi < 4; mi++)
#pragma unroll
                    for (int ni = 0; ni < 4; ni++)
                        mma16816(cu[mi][ni], af[mi], bf[ni]);
            }
        }
        __syncthreads();
    }

    // epilogue: h = fp16(silu(g) * u), written directly (no gbuf)
#pragma unroll
    for (int mi = 0; mi < 4; mi++) {
#pragma unroll
        for (int ni = 0; ni < 4; ni++) {
            int rrow = r0 + wm * 64 + mi * 16 + gid;
            int cc = nb + wn * 32 + ni * 8 + tig * 2;
            float* pg = cg[mi][ni];
            float* pu = cu[mi][ni];
            if (rrow < rend) {
                __half2 h = __floats2half2_rn(silu_f(pg[0]) * pu[0],
                                              silu_f(pg[1]) * pu[1]);
                *(__half2*)(g_h + (size_t)rrow * FDIM + cc) = h;
            }
            if (rrow + 8 < rend) {
                __half2 h = __floats2half2_rn(silu_f(pg[2]) * pu[2],
                                              silu_f(pg[3]) * pu[3]);
                *(__half2*)(g_h + (size_t)(rrow + 8) * FDIM + cc) = h;
            }
        }
    }
}

// ------------------- down GEMM (A = g_h) -----------------------------------
// MODE 1: plain store to out. MODE 2: scatter out[perm[r]] += v.
template <int MODE>
__global__ __launch_bounds__(256) void k_gemm_down(
    const __half* __restrict__ B0, long bexp_stride, int offsel,
    float* __restrict__ out)
{
    __shared__ __half As[2 * ASZ];
    __shared__ __half Bs[2 * BSZ];

    const int* offs = offsel ? g_off_shared : g_off;
    int e    = blockIdx.z;
    int r0   = offs[e] + blockIdx.y * BM;
    int rend = offs[e + 1];
    if (r0 >= rend) return;

    const __half* A = g_h;
    const __half* B = B0 + (long)e * bexp_stride;
    int nb = blockIdx.x * BN;

    int tid = threadIdx.x;
    int lane = tid & 31, wid = tid >> 5;
    int wm = wid & 1, wn = wid >> 1;
    int gid = lane >> 2, tig = lane & 3;

    int a_row0 = (tid * 2) >> 2,     a_cc0 = (tid * 2) & 3;
    int a_row1 = (tid * 2 + 1) >> 2, a_cc1 = (tid * 2 + 1) & 3;
    int b_row = tid >> 3, b_c = (tid & 7) * 16;

    int rr = lane & 7, s1 = (lane >> 3) & 1, s2 = lane >> 4;

    float c[4][4][4];
#pragma unroll
    for (int mi = 0; mi < 4; mi++)
#pragma unroll
        for (int ni = 0; ni < 4; ni++)
#pragma unroll
            for (int j = 0; j < 4; j++) c[mi][ni][j] = 0.f;

    auto issue_tiles = [&](int kb, int st) {
        {
            int gr = r0 + a_row0;
            int ok = gr < rend;
            cp16(As + st * ASZ + a_row0 * ASTRIDE + a_cc0 * 8,
                 A + (size_t)(ok ? gr : r0) * FDIM + kb * BK + a_cc0 * 8,
                 ok ? 16 : 0);
            gr = r0 + a_row1;
            ok = gr < rend;
            cp16(As + st * ASZ + a_row1 * ASTRIDE + a_cc1 * 8,
                 A + (size_t)(ok ? gr : r0) * FDIM + kb * BK + a_cc1 * 8,
                 ok ? 16 : 0);
        }
        {
            const __half* src = B + (size_t)(kb * BK + b_row) * 2048 + nb + b_c;
            __half* dst = Bs + st * BSZ + b_row * BSTRIDE_H + b_c;
            cp16(dst,     src,     16);
            cp16(dst + 8, src + 8, 16);
        }
        cp_commit();
    };

    const int NKB = FDIM / BK;   // 64
    issue_tiles(0, 0);

    for (int kb = 0; kb < NKB; kb++) {
        int cur = kb & 1;
        if (kb + 1 < NKB) {
            issue_tiles(kb + 1, cur ^ 1);
            cp_wait<1>();
        } else {
            cp_wait<0>();
        }
        __syncthreads();

        const __half* Ast = As + cur * ASZ;
        const __half* Bst = Bs + cur * BSZ;

#pragma unroll
        for (int ks = 0; ks < 2; ks++) {
            int k0 = ks * 16;
            uint32_t af[4][4];
#pragma unroll
            for (int mi = 0; mi < 4; mi++) {
                int m = wm * 64 + mi * 16 + rr + s1 * 8;
                ldsm_x4(af[mi], Ast + m * ASTRIDE + k0 + s2 * 8);
            }
            uint32_t bf[4][2];
#pragma unroll
            for (int nj = 0; nj < 2; nj++) {
                int kk = k0 + s1 * 8 + rr;
                int n0 = wn * 32 + nj * 16 + s2 * 8;
                uint32_t q[4];
                ldsm_x4_t(q, Bst + kk * BSTRIDE_H + n0);
                bf[nj * 2][0] = q[0]; bf[nj * 2][1] = q[1];
                bf[nj * 2 + 1][0] = q[2]; bf[nj * 2 + 1][1] = q[3];
            }
#pragma unroll
            for (int mi = 0; mi < 4; mi++)
#pragma unroll
                for (int ni = 0; ni < 4; ni++)
                    mma16816(c[mi][ni], af[mi], bf[ni]);
        }
        __syncthreads();
    }

#pragma unroll
    for (int mi = 0; mi < 4; mi++) {
#pragma unroll
        for (int ni = 0; ni < 4; ni++) {
            int rrow = r0 + wm * 64 + mi * 16 + gid;
            int cc = nb + wn * 32 + ni * 8 + tig * 2;
            float* cp = c[mi][ni];
            if (MODE == 1) {
                if (rrow < rend) {
                    out[(size_t)rrow * DMODEL + cc]     = cp[0];
                    out[(size_t)rrow * DMODEL + cc + 1] = cp[1];
                }
                if (rrow + 8 < rend) {
                    out[(size_t)(rrow + 8) * DMODEL + cc]     = cp[2];
                    out[(size_t)(rrow + 8) * DMODEL + cc + 1] = cp[3];
                }
            } else {
                if (rrow < rend) {
                    int tk = g_perm[rrow];
                    float* o = out + (size_t)tk * DMODEL + cc;
                    o[0] += cp[0]; o[1] += cp[1];
                }
                if (rrow + 8 < rend) {
                    int tk = g_perm[rrow + 8];
                    float* o = out + (size_t)tk * DMODEL + cc;
                    o[0] += cp[2]; o[1] += cp[3];
                }
            }
        }
    }
}

// ---------------------------------------------------------------------------
extern "C" void kernel_launch(void* const* d_in, const int* in_sizes, int n_in,
                              void* d_out, int out_size) {
    const float* x   = (const float*)d_in[0];
    const float* rw  = (const float*)d_in[1];
    const float* gw  = (const float*)d_in[2];
    const float* uw  = (const float*)d_in[3];
    const float* dw  = (const float*)d_in[4];
    const float* sgw = (const float*)d_in[5];
    const float* suw = (const float*)d_in[6];
    const float* sdw = (const float*)d_in[7];
    float* out = (float*)d_out;

    cudaFuncSetAttribute(k_gemm_gu, cudaFuncAttributeMaxDynamicSharedMemorySize,
                         GU_SMEM_BYTES);

    __half *wg16, *wu16, *wd16, *sg16, *su16, *sd16;
    cudaGetSymbolAddress((void**)&wg16, g_wg16);
    cudaGetSymbolAddress((void**)&wu16, g_wu16);
    cudaGetSymbolAddress((void**)&wd16, g_wd16);
    cudaGetSymbolAddress((void**)&sg16, g_sg16);
    cudaGetSymbolAddress((void**)&su16, g_su16);
    cudaGetSymbolAddress((void**)&sd16, g_sd16);

    const size_t NR4 = (size_t)NEXP * DMODEL * FDIM / 4;
    const size_t NS4 = (size_t)DMODEL * FDIM / 4;
    ConvJobs cj;
    cj.src[0] = gw;  cj.dst[0] = wg16; cj.n4[0] = NR4;
    cj.src[1] = uw;  cj.dst[1] = wu16; cj.n4[1] = NR4;
    cj.src[2] = dw;  cj.dst[2] = wd16; cj.n4[2] = NR4;
    cj.src[3] = sgw; cj.dst[3] = sg16; cj.n4[3] = NS4;
    cj.src[4] = suw; cj.dst[4] = su16; cj.n4[4] = NS4;
    cj.src[5] = sdw; cj.dst[5] = sd16; cj.n4[5] = NS4;

    k_conv_all<<<4096, 256>>>(cj);                                     // 1 (+zero)
    k_router<<<T_TOK, 128>>>(x, rw);                                   // 2
    k_scan<<<1, 1>>>();                                                // 3
    // 4: fused shared gate+up  <-- ncu captures launch #4
    k_gemm_gu<<<dim3(FDIM / BN, T_TOK / BM, 1), 256, GU_SMEM_BYTES>>>(
        1, sg16, su16, 0L, 1);
    k_gather<<<T_TOK, 128>>>(x);                                       // 5
    k_gemm_down<1><<<dim3(DMODEL / BN, T_TOK / BM, 1), 256>>>(         // 6 shared down
        sd16, 0L, 1, out);
    k_gemm_gu<<<dim3(FDIM / BN, T_TOK / BM, NEXP), 256, GU_SMEM_BYTES>>>( // 7 routed gate+up
        0, wg16, wu16, (long)DMODEL * FDIM, 0);
    k_gemm_down<2><<<dim3(DMODEL / BN, T_TOK / BM, NEXP), 256>>>(      // 8 routed down
        wd16, (long)FDIM * DMODEL, 0, out);
}